// round 2
// baseline (speedup 1.0000x reference)
#include <cuda_runtime.h>
#include <math.h>

#define G     1024
#define GM    (G - 1)
#define NA    262144
#define NC    8
#define DT_F  0.1f
#define DEC_F 0.99f
#define SANG  0.6f
#define SLEN  3.0f

// Scratch (static device globals; no allocation anywhere)
__device__ float g_tmp1[NC * G * G];      // horizontal 3-sum, (C,G,G)       32 MB
__device__ float g_box[G * G * NC];       // 3x3 box sum, transposed (G,G,C) 32 MB
__device__ float g_dpher[NA * NC];        // per-agent pheromone delta        8 MB
__device__ int   g_winner[G * G];         // last-writer agent index + 1      4 MB (zero-init)

// ---------------------------------------------------------------------------
// Pass 1: horizontal wrapped 3-sum along y.  tmp1[c][x][y] = L[y-1]+L[y]+L[y+1]
// ---------------------------------------------------------------------------
__global__ void k_hsum(const float* __restrict__ lat) {
    int t   = blockIdx.x * blockDim.x + threadIdx.x;   // C*G*G/4 threads
    int y0  = (t & 255) << 2;                          // 4 consecutive y per thread
    int row = t >> 8;                                  // c*G + x
    const float* r = lat + (size_t)row * G;
    float4 m = *(const float4*)(r + y0);
    float lm = __ldg(r + ((y0 + GM) & GM));
    float rp = __ldg(r + ((y0 + 4) & GM));
    float4 o;
    o.x = lm  + m.x + m.y;
    o.y = m.x + m.y + m.z;
    o.z = m.y + m.z + m.w;
    o.w = m.z + m.w + rp;
    *(float4*)(g_tmp1 + (size_t)row * G + y0) = o;
}

// ---------------------------------------------------------------------------
// Pass 2: vertical wrapped 3-sum along x + transpose to (x,y,c): one sensor
// lookup becomes 32 contiguous bytes (all 8 channels in one L2 sector).
// ---------------------------------------------------------------------------
__global__ void k_vsum() {
    int t  = blockIdx.x * blockDim.x + threadIdx.x;    // G*G threads
    int y  = t & GM;
    int x  = t >> 10;
    int xm = (x + GM) & GM;
    int xp = (x + 1) & GM;
    float o[NC];
#pragma unroll
    for (int c = 0; c < NC; c++) {
        const float* p = g_tmp1 + (size_t)c * (G * G);
        o[c] = p[xm * G + y] + p[x * G + y] + p[xp * G + y];
    }
    float4* dst = (float4*)(g_box + (size_t)t * NC);
    dst[0] = make_float4(o[0], o[1], o[2], o[3]);
    dst[1] = make_float4(o[4], o[5], o[6], o[7]);
}

// ---------------------------------------------------------------------------
// Pass 3: per-agent sense + MLP + pos/vel output + deposit claim (last wins).
// ---------------------------------------------------------------------------
__global__ __launch_bounds__(256) void k_agent(
    const float* __restrict__ pos, const float* __restrict__ vel,
    const float* __restrict__ W1,  const float* __restrict__ b1,
    const float* __restrict__ W2,  const float* __restrict__ b2,
    float* __restrict__ out)
{
    __shared__ float sW1[24 * 64];
    __shared__ float sB1[64];
    __shared__ float sW2[64 * 12];   // 10 outputs padded to 12 for float4 rows
    __shared__ float sB2[12];

    int tid = threadIdx.x;
    for (int i = tid; i < 24 * 64; i += 256) sW1[i] = __ldg(W1 + i);
    if (tid < 64) sB1[tid] = __ldg(b1 + tid);
    for (int i = tid; i < 64 * 12; i += 256) {
        int k = i / 12, m = i - k * 12;
        sW2[i] = (m < 10) ? __ldg(W2 + k * 10 + m) : 0.0f;
    }
    if (tid < 12) sB2[tid] = (tid < 10) ? __ldg(b2 + tid) : 0.0f;
    __syncthreads();

    int a = blockIdx.x * 256 + tid;
    float px = pos[a],      py = pos[NA + a];
    float vx = vel[a],      vy = vel[NA + a];
    float th = atan2f(vy, vx);

    float x[24];
    const float offs[3] = {0.0f, SANG, -SANG};
#pragma unroll
    for (int s = 0; s < 3; s++) {
        float sa, ca;
        sincosf(th + offs[s], &sa, &ca);
        int cx = (int)rintf(px + SLEN * ca);
        int cy = (int)rintf(py + SLEN * sa);
        int ix = cx & GM;              // == Python % for negatives (G pow2)
        int iy = cy & GM;
        const float4* bp = (const float4*)(g_box + ((size_t)(ix * G + iy)) * NC);
        float4 u = bp[0], v = bp[1];
        x[s * 8 + 0] = u.x; x[s * 8 + 1] = u.y; x[s * 8 + 2] = u.z; x[s * 8 + 3] = u.w;
        x[s * 8 + 4] = v.x; x[s * 8 + 5] = v.y; x[s * 8 + 6] = v.z; x[s * 8 + 7] = v.w;
    }

    // Layer 1: h = tanh(x @ W1 + b1); fully unrolled, float4 across hidden dim
    float h[64];
#pragma unroll
    for (int jq = 0; jq < 16; jq++) {
        float4 acc = *(const float4*)&sB1[jq * 4];
#pragma unroll
        for (int k = 0; k < 24; k++) {
            float4 w = *(const float4*)&sW1[k * 64 + jq * 4];
            acc.x = fmaf(x[k], w.x, acc.x);
            acc.y = fmaf(x[k], w.y, acc.y);
            acc.z = fmaf(x[k], w.z, acc.z);
            acc.w = fmaf(x[k], w.w, acc.w);
        }
        h[jq * 4 + 0] = tanhf(acc.x);
        h[jq * 4 + 1] = tanhf(acc.y);
        h[jq * 4 + 2] = tanhf(acc.z);
        h[jq * 4 + 3] = tanhf(acc.w);
    }

    // Layer 2: o = h @ W2 + b2 (10 real outputs, padded to 12)
    float4 aA = *(const float4*)&sB2[0];
    float4 aB = *(const float4*)&sB2[4];
    float4 aC = *(const float4*)&sB2[8];
#pragma unroll
    for (int k = 0; k < 64; k++) {
        float hk = h[k];
        const float4* wr = (const float4*)&sW2[k * 12];
        float4 w0 = wr[0], w1 = wr[1], w2 = wr[2];
        aA.x = fmaf(hk, w0.x, aA.x); aA.y = fmaf(hk, w0.y, aA.y);
        aA.z = fmaf(hk, w0.z, aA.z); aA.w = fmaf(hk, w0.w, aA.w);
        aB.x = fmaf(hk, w1.x, aB.x); aB.y = fmaf(hk, w1.y, aB.y);
        aB.z = fmaf(hk, w1.z, aB.z); aB.w = fmaf(hk, w1.w, aB.w);
        aC.x = fmaf(hk, w2.x, aC.x); aC.y = fmaf(hk, w2.y, aC.y);
    }

    float nvx = aA.x, nvy = aA.y;
    float npx = px + nvx * DT_F;
    float npy = py + nvy * DT_F;
    npx -= floorf(npx * (1.0f / G)) * (float)G;   // x - floor(x/G)*G (jnp.mod fp32)
    npy -= floorf(npy * (1.0f / G)) * (float)G;

    out[a]          = npx;
    out[NA + a]     = npy;
    out[2 * NA + a] = nvx;
    out[3 * NA + a] = nvy;

    float4* dp = (float4*)(g_dpher + (size_t)a * NC);
    dp[0] = make_float4(aA.z, aA.w, aB.x, aB.y);
    dp[1] = make_float4(aB.z, aB.w, aC.x, aC.y);

    int pix = (int)rintf(px) & GM;
    int piy = (int)rintf(py) & GM;
    atomicMax(&g_winner[pix * G + piy], a + 1);   // "last update wins" (max agent idx)
}

// ---------------------------------------------------------------------------
// Pass 4: resolve deposits + decay; resets g_winner so replays are identical.
// ---------------------------------------------------------------------------
__global__ void k_update(const float* __restrict__ lat, float* __restrict__ out) {
    int t = blockIdx.x * blockDim.x + threadIdx.x;     // G*G threads
    int w = g_winner[t];
    if (w) g_winner[t] = 0;
    float dp[NC];
    if (w) {
        const float4* q = (const float4*)(g_dpher + (size_t)(w - 1) * NC);
        float4 d0 = q[0], d1 = q[1];
        dp[0] = d0.x; dp[1] = d0.y; dp[2] = d0.z; dp[3] = d0.w;
        dp[4] = d1.x; dp[5] = d1.y; dp[6] = d1.z; dp[7] = d1.w;
    }
    float* o = out + 4 * NA;
#pragma unroll
    for (int c = 0; c < NC; c++) {
        float v = lat[(size_t)c * (G * G) + t];
        if (w) v = fmaxf(v + DT_F * dp[c], 0.0f);
        o[(size_t)c * (G * G) + t] = v * DEC_F;
    }
}

// ---------------------------------------------------------------------------
extern "C" void kernel_launch(void* const* d_in, const int* in_sizes, int n_in,
                              void* d_out, int out_size) {
    const float* pos = (const float*)d_in[0];
    const float* vel = (const float*)d_in[1];
    const float* lat = (const float*)d_in[2];
    const float* W1  = (const float*)d_in[3];
    const float* b1  = (const float*)d_in[4];
    const float* W2  = (const float*)d_in[5];
    const float* b2  = (const float*)d_in[6];
    float* out = (float*)d_out;

    k_hsum  <<<(NC * G * G / 4) / 256, 256>>>(lat);
    k_vsum  <<<(G * G) / 256, 256>>>();
    k_agent <<<NA / 256, 256>>>(pos, vel, W1, b1, W2, b2, out);
    k_update<<<(G * G) / 256, 256>>>(lat, out);
}